// round 1
// baseline (speedup 1.0000x reference)
#include <cuda_runtime.h>

#define BB 1024
#define LL 512
#define TT 50
#define TSTART 48
#define TSTOP 49
#define LOG2E 1.4426950408889634f
#define LN2F  0.6931471805599453f

__device__ float g_partial[BB];

__device__ __forceinline__ unsigned long long pack2(float x, float y){
    unsigned long long r;
    asm("mov.b64 %0, {%1,%2};" : "=l"(r) : "f"(x), "f"(y));
    return r;
}
__device__ __forceinline__ void unpack2(unsigned long long v, float &x, float &y){
    asm("mov.b64 {%0,%1}, %2;" : "=f"(x), "=f"(y) : "l"(v));
}
// Packed dual FMA (Blackwell f32x2 pipe): d = a*b + d  (2 lanes per instr)
__device__ __forceinline__ void ffma2(unsigned long long &d, unsigned long long a, unsigned long long b){
    asm("fma.rn.f32x2 %0, %1, %2, %0;" : "+l"(d) : "l"(a), "l"(b));
}

__global__ void __launch_bounds__(128)
crf_fwd(const float* __restrict__ logits,
        const float* __restrict__ trans,
        const int*   __restrict__ labels,
        const int*   __restrict__ lens)
{
    __shared__ unsigned long long sbuf[4][2][32];   // per-warp double-buffered v broadcast (64 floats)
    const int warp = threadIdx.x >> 5;
    const int lane = threadIdx.x & 31;
    const int b = blockIdx.x * 4 + warp;
    if (b >= BB) return;

    const int j0 = lane;
    const int j1 = lane + 32;
    const bool hasJ1 = (j1 < TT);          // lanes 0..17 own a second row

    // zero broadcast buffers (slots 50..63 must stay 0 forever)
    sbuf[warp][0][lane] = 0ull;
    sbuf[warp][1][lane] = 0ull;

    // E = exp(transitions), rows j0 and j1, packed as f32x2 pairs in registers.
    unsigned long long E0[25], E1[25];
#pragma unroll
    for (int p = 0; p < 25; p++){
        float a = exp2f(LOG2E * __ldg(&trans[j0*TT + 2*p    ]));
        float c = exp2f(LOG2E * __ldg(&trans[j0*TT + 2*p + 1]));
        E0[p] = pack2(a, c);
        float d0 = 0.f, d1 = 0.f;
        if (hasJ1){
            d0 = exp2f(LOG2E * __ldg(&trans[j1*TT + 2*p    ]));
            d1 = exp2f(LOG2E * __ldg(&trans[j1*TT + 2*p + 1]));
        }
        E1[p] = pack2(d0, d1);
    }

    const int len = lens[b];
    const float* __restrict__ row    = logits + (long long)b * LL * TT;
    const int*   __restrict__ labrow = labels + (long long)b * LL;

    // software prefetch pipeline (distance 3) of logits rows, lane-sliced
    float a0, a1, b0, b1, c0, c1;
    {
        int t1 = (1 < len) ? 1 : len - 1;
        int t2 = (2 < len) ? 2 : len - 1;
        a0 = row[0*TT + j0];  a1 = hasJ1 ? row[0*TT + j1] : 0.f;
        b0 = row[t1*TT + j0]; b1 = hasJ1 ? row[t1*TT + j1] : 0.f;
        c0 = row[t2*TT + j0]; c1 = hasJ1 ? row[t2*TT + j1] : 0.f;
    }

    // v = exp(alpha) * 2^{-off2};  alpha0: start=0, rest = -1e4 -> v underflows to 0 (same as fp32 ref)
    float vlo = 0.f;
    float vhi = (j1 == TSTART) ? 1.f : 0.f;
    float off2 = 0.f;                 // exact integer binary exponent accumulator
    float em = 0.f, tr = 0.f;
    int   labPrev = TSTART;

    float* wb0 = (float*)&sbuf[warp][0][0];
    float* wb1 = (float*)&sbuf[warp][1][0];
    int phase = 0;

    for (int t = 0; t < len; t++){
        // emission-rate factors for this step (independent of recurrence chain)
        float P0 = exp2f(LOG2E * a0);
        float P1 = exp2f(LOG2E * a1);

        // ---- score accumulation (uniform across lanes) ----
        int lab = __ldg(&labrow[t]);
        float e0s = __shfl_sync(0xffffffffu, a0, lab & 31);
        float e1s = __shfl_sync(0xffffffffu, a1, lab & 31);
        em += (lab < 32) ? e0s : e1s;
        tr += __ldg(&trans[lab*TT + labPrev]);
        labPrev = lab;

        // ---- broadcast v through shared (double-buffered) ----
        float* wb = phase ? wb1 : wb0;
        wb[j0] = vlo;
        if (hasJ1) wb[j1] = vhi;
        __syncwarp();

        const unsigned long long* vb = (const unsigned long long*)wb;
        unsigned long long acc0a = 0ull, acc0b = 0ull, acc1a = 0ull, acc1b = 0ull;
#pragma unroll
        for (int p = 0; p < 25; p++){
            unsigned long long v2 = vb[p];           // LDS.64 broadcast (uniform address)
            if (p & 1){ ffma2(acc0b, E0[p], v2); ffma2(acc1b, E1[p], v2); }
            else      { ffma2(acc0a, E0[p], v2); ffma2(acc1a, E1[p], v2); }
        }
        float x0, x1, y0, y1;
        unpack2(acc0a, x0, x1); unpack2(acc0b, y0, y1);
        float s0 = (x0 + y0) + (x1 + y1);
        unpack2(acc1a, x0, x1); unpack2(acc1b, y0, y1);
        float s1 = (x0 + y0) + (x1 + y1);

        vlo = P0 * s0;
        vhi = P1 * s1;

        // ---- exact power-of-2 renorm every 4 steps (overflow-safe: growth < 2^20/step) ----
        if ((t & 3) == 3){
            float m = fmaxf(vlo, vhi);
#pragma unroll
            for (int o = 16; o; o >>= 1) m = fmaxf(m, __shfl_xor_sync(0xffffffffu, m, o));
            int k = (__float_as_int(m) >> 23) - 127;
            off2 += (float)k;
            float scale = __int_as_float((127 - k) << 23);
            vlo *= scale;
            vhi *= scale;
        }

        phase ^= 1;
        // rotate prefetch queue, fetch row t+3 (clamped)
        a0 = b0; a1 = b1; b0 = c0; b1 = c1;
        int tn = t + 3; if (tn >= len) tn = len - 1;
        c0 = row[tn*TT + j0];
        c1 = hasJ1 ? row[tn*TT + j1] : 0.f;
    }

    // final transition into STOP
    tr += __ldg(&trans[TSTOP*TT + labPrev]);

    // partition = ln2 * (off2 + log2( sum_j v_j * exp(trans[STOP,j]) ))
    float z0 = exp2f(LOG2E * __ldg(&trans[TSTOP*TT + j0]));
    float z1 = hasJ1 ? exp2f(LOG2E * __ldg(&trans[TSTOP*TT + j1])) : 0.f;
    float s  = vlo * z0 + vhi * z1;
#pragma unroll
    for (int o = 16; o; o >>= 1) s += __shfl_xor_sync(0xffffffffu, s, o);

    if (lane == 0){
        float part = LN2F * (off2 + log2f(s));
        g_partial[b] = part - em - tr;
    }
}

__global__ void crf_reduce(float* __restrict__ out){
    __shared__ float sm[256];
    int tid = threadIdx.x;
    float s = 0.f;
    for (int i = tid; i < BB; i += 256) s += g_partial[i];
    sm[tid] = s;
    __syncthreads();
#pragma unroll
    for (int o = 128; o; o >>= 1){
        if (tid < o) sm[tid] += sm[tid + o];
        __syncthreads();
    }
    if (tid == 0) out[0] = sm[0] * (1.f / BB);
}

extern "C" void kernel_launch(void* const* d_in, const int* in_sizes, int n_in,
                              void* d_out, int out_size)
{
    const float* logits = (const float*)d_in[0];
    const float* trans  = (const float*)d_in[1];
    const int*   labels = (const int*)d_in[2];
    const int*   lens   = (const int*)d_in[3];
    crf_fwd<<<BB / 4, 128>>>(logits, trans, labels, lens);
    crf_reduce<<<1, 256>>>((float*)d_out);
}

// round 4
// speedup vs baseline: 1.3456x; 1.3456x over previous
#include <cuda_runtime.h>
#include <cstdint>

#define BB 1024
#define LL 512
#define TT 50
#define TSTART 48
#define TSTOP 49
#define LOG2E 1.4426950408889634f
#define LN2F  0.6931471805599453f

__device__ __forceinline__ float ex2f(float x){
    float r; asm("ex2.approx.ftz.f32 %0, %1;" : "=f"(r) : "f"(x)); return r;
}
__device__ __forceinline__ unsigned long long pack2(float x, float y){
    unsigned long long r; asm("mov.b64 %0, {%1,%2};" : "=l"(r) : "f"(x), "f"(y)); return r;
}
__device__ __forceinline__ void unpack2(unsigned long long v, float &x, float &y){
    asm("mov.b64 {%0,%1}, %2;" : "=f"(x), "=f"(y) : "l"(v));
}
__device__ __forceinline__ void ffma2(unsigned long long &d, unsigned long long a, unsigned long long b){
    asm("fma.rn.f32x2 %0, %1, %2, %0;" : "+l"(d) : "l"(a), "l"(b));
}
__device__ __forceinline__ unsigned long long add2(unsigned long long a, unsigned long long b){
    unsigned long long r; asm("add.rn.f32x2 %0, %1, %2;" : "=l"(r) : "l"(a), "l"(b)); return r;
}
// Warp max of NONNEGATIVE floats via integer redux (bit pattern of x>=0 is order-isomorphic).
__device__ __forceinline__ uint32_t redux_max_bits(float x){
    uint32_t r; asm("redux.sync.max.u32 %0, %1, 0xffffffff;" : "=r"(r) : "r"(__float_as_uint(x))); return r;
}
__device__ __forceinline__ uint32_t saddr(const void* p){
    return (uint32_t)__cvta_generic_to_shared(p);
}
__device__ __forceinline__ void cp8(uint32_t dst, const float* src){
    asm volatile("cp.async.ca.shared.global [%0], [%1], 8;" :: "r"(dst), "l"(src));
}
__device__ __forceinline__ void cp_commit(){ asm volatile("cp.async.commit_group;"); }
__device__ __forceinline__ void cp_wait6(){ asm volatile("cp.async.wait_group 6;"); }

__global__ void zero_out(float* o){ if (threadIdx.x == 0) o[0] = 0.f; }

__global__ void __launch_bounds__(128)
crf_fwd(const float* __restrict__ logits,
        const float* __restrict__ trans,
        const int*   __restrict__ labels,
        const int*   __restrict__ lens,
        float* __restrict__ out)
{
    __shared__ float ring[4][8][64];   // per-warp 8-deep logits row ring (rows padded to 256B)
    __shared__ float vbuf[4][2][64];   // per-warp double-buffered v broadcast

    const int warp = threadIdx.x >> 5;
    const int lane = threadIdx.x & 31;
    const int b = blockIdx.x * 4 + warp;

    const int j0 = lane;
    const int j1 = lane + 32;
    const bool hasJ1 = (j1 < TT);      // lanes 0..17 own a second row

    // E = exp(transitions), rows j0 / j1, packed f32x2, in registers (100 regs)
    unsigned long long E0[25], E1[25];
#pragma unroll
    for (int p = 0; p < 25; p++){
        E0[p] = pack2(ex2f(LOG2E * __ldg(&trans[j0*TT + 2*p    ])),
                      ex2f(LOG2E * __ldg(&trans[j0*TT + 2*p + 1])));
        float d0 = 0.f, d1 = 0.f;
        if (hasJ1){
            d0 = ex2f(LOG2E * __ldg(&trans[j1*TT + 2*p    ]));
            d1 = ex2f(LOG2E * __ldg(&trans[j1*TT + 2*p + 1]));
        }
        E1[p] = pack2(d0, d1);
    }

    const int len = lens[b];
    const float* __restrict__ row    = logits + (long long)b * LL * TT;
    const int*   __restrict__ labrow = labels + (long long)b * LL;

    // ---- prologue: prefetch rows 0..6 into ring slots 0..6 (one commit group per row)
#pragma unroll
    for (int q = 0; q < 7; q++){
        int tq = q < len ? q : len - 1;
        if (lane < 25)
            cp8(saddr(&ring[warp][q][0]) + lane * 8u, row + (long long)tq * TT + lane * 2);
        cp_commit();
    }

    // v = exp(alpha) * 2^{-off}; alpha0: START=0, rest -> 0 mass (underflow, same as fp32 ref)
    float vlo = 0.f;
    float vhi = (j1 == TSTART) ? 1.f : 0.f;
    int   off = 0;
    float em = 0.f, tr = 0.f;
    int   labPrev = TSTART;
    int   phase = 0;

    for (int t = 0; t < len; t++){
        const int slot = t & 7;

        // publish v for this step
        float* wb = &vbuf[warp][phase][0];
        wb[j0] = vlo;
        if (hasJ1) wb[j1] = vhi;

        cp_wait6();          // row t's group complete (this thread's copies)
        __syncwarp();        // cross-lane: v visible + all lanes' copies of row t visible

        // issue prefetch of row t+7 into slot (t+7)&7 (!= slot; that slot's reads finished pre-sync)
        {
            int tn = t + 7; if (tn >= len) tn = len - 1;
            int ps = (t + 7) & 7;
            if (lane < 25)
                cp8(saddr(&ring[warp][ps][0]) + lane * 8u, row + (long long)tn * TT + lane * 2);
            cp_commit();
        }

        const float* srow = &ring[warp][slot][0];
        float a0 = srow[j0];
        float a1 = hasJ1 ? srow[j1] : 0.f;

        // score accumulation (uniform across lanes; off the recurrence chain)
        int lab = __ldg(&labrow[t]);
        em += srow[lab];                              // uniform LDS broadcast
        tr += __ldg(&trans[lab*TT + labPrev]);
        labPrev = lab;

        float P0 = ex2f(LOG2E * a0);
        float P1 = ex2f(LOG2E * a1);

        // mat-vec: 25 f32x2 FMAs into 4 independent accumulator chains (depth 7)
        const unsigned long long* vb = (const unsigned long long*)wb;
        unsigned long long A0[4] = {0ull,0ull,0ull,0ull};
        unsigned long long A1[4] = {0ull,0ull,0ull,0ull};
#pragma unroll
        for (int p = 0; p < 25; p++){
            unsigned long long v2 = vb[p];            // LDS.64 uniform broadcast
            ffma2(A0[p & 3], E0[p], v2);
            ffma2(A1[p & 3], E1[p], v2);
        }
        unsigned long long t0 = add2(add2(A0[0], A0[1]), add2(A0[2], A0[3]));
        unsigned long long t1 = add2(add2(A1[0], A1[1]), add2(A1[2], A1[3]));
        float x, y;
        unpack2(t0, x, y); float s0 = x + y;
        unpack2(t1, x, y); float s1 = x + y;

        vlo = P0 * s0;
        vhi = P1 * s1;

        // exact power-of-2 renorm every 4 steps (worst-case growth < 2^21/step -> safe)
        if ((t & 3) == 3){
            uint32_t mb = redux_max_bits(fmaxf(vlo, vhi));  // warp max via u32 redux (v >= 0)
            int k = (int)(mb >> 23) - 127;
            k = max(k, -126);                         // guard: never inject a non-finite scale
            off += k;
            float sc = __int_as_float((127 - k) << 23);
            vlo *= sc;
            vhi *= sc;
        }
        phase ^= 1;
    }

    // final transition into STOP
    tr += __ldg(&trans[TSTOP*TT + labPrev]);

    // partition = ln2 * (off + log2( sum_j v_j * exp(trans[STOP,j]) ))
    float z0 = ex2f(LOG2E * __ldg(&trans[TSTOP*TT + j0]));
    float z1 = hasJ1 ? ex2f(LOG2E * __ldg(&trans[TSTOP*TT + j1])) : 0.f;
    float s  = vlo * z0 + vhi * z1;
#pragma unroll
    for (int o = 16; o; o >>= 1) s += __shfl_xor_sync(0xffffffffu, s, o);

    if (lane == 0){
        float part = LN2F * ((float)off + log2f(s));
        atomicAdd(out, (part - em - tr) * (1.0f / BB));
    }
}

extern "C" void kernel_launch(void* const* d_in, const int* in_sizes, int n_in,
                              void* d_out, int out_size)
{
    const float* logits = (const float*)d_in[0];
    const float* trans  = (const float*)d_in[1];
    const int*   labels = (const int*)d_in[2];
    const int*   lens   = (const int*)d_in[3];
    float* out = (float*)d_out;
    zero_out<<<1, 32>>>(out);
    crf_fwd<<<BB / 4, 128>>>(logits, trans, labels, lens, out);
}